// round 2
// baseline (speedup 1.0000x reference)
#include <cuda_runtime.h>
#include <cstdint>

#define IND       1024
#define ODIM      128
#define BATCHN    65536
#define BM        128
#define KC        32                 // fp32 elems per K-chunk (one 128B row)
#define NITER     (IND / KC)         // 32
#define NS        3
#define NTHR      256

#define SM_COEF     0                // a0[128], a1[128], bias[128] = 1536B
#define SM_STAGE    2048
#define STAGE_BYTES 65536            // 4 tiles x 16KB (x, y, w0, w1)
#define TO_X        0
#define TO_Y        16384
#define TO_W0       32768
#define TO_W1       49152
#define SMEM_TOTAL  (SM_STAGE + NS * STAGE_BYTES)   // 198656 B
#define EXP         132              // exchange buffer pitch (floats)

typedef uint32_t U32;

__device__ float g_W0n[ODIM * IND];
__device__ float g_W1n[ODIM * IND];

// ---------------- PTX helpers ----------------

static __device__ __forceinline__ U32 s2u(const void* p) {
    U32 a;
    asm("{ .reg .u64 t; cvta.to.shared.u64 t, %1; cvt.u32.u64 %0, t; }" : "=r"(a) : "l"(p));
    return a;
}

static __device__ __forceinline__ void cp16(U32 dst, const void* src) {
    asm volatile("cp.async.cg.shared.global [%0], [%1], 16;" :: "r"(dst), "l"(src));
}
static __device__ __forceinline__ void cp_commit() {
    asm volatile("cp.async.commit_group;" ::: "memory");
}
template <int N> static __device__ __forceinline__ void cp_wait() {
    asm volatile("cp.async.wait_group %0;" :: "n"(N) : "memory");
}

static __device__ __forceinline__ void ldsm4(U32& r0, U32& r1, U32& r2, U32& r3, U32 addr) {
    asm volatile("ldmatrix.sync.aligned.m8n8.x4.shared.b16 {%0,%1,%2,%3}, [%4];"
                 : "=r"(r0), "=r"(r1), "=r"(r2), "=r"(r3) : "r"(addr));
}

static __device__ __forceinline__ void mma8(float* c, U32 a0, U32 a1, U32 a2, U32 a3,
                                            U32 b0, U32 b1) {
    asm volatile("mma.sync.aligned.m16n8k8.row.col.f32.tf32.tf32.f32 "
                 "{%0,%1,%2,%3}, {%4,%5,%6,%7}, {%8,%9}, {%0,%1,%2,%3};"
                 : "+f"(c[0]), "+f"(c[1]), "+f"(c[2]), "+f"(c[3])
                 : "r"(a0), "r"(a1), "r"(a2), "r"(a3), "r"(b0), "r"(b1));
}

// ---------------- weight normalization ----------------
// OWNNorm rows: w' = (w - mean(w)) * rsqrt(sum((w-mean)^2))
__global__ void normalize_kernel(const float* __restrict__ w) {
    int row  = blockIdx.x & (ODIM - 1);
    int half = blockIdx.x >> 7;
    const float* src = w + (size_t)row * (2 * IND) + (size_t)half * IND;
    float* dst = (half ? g_W1n : g_W0n) + (size_t)row * IND;
    int t = threadIdx.x;  // 256 threads
    float v[4], s = 0.f, s2 = 0.f;
#pragma unroll
    for (int i = 0; i < 4; ++i) { v[i] = src[t + 256 * i]; s += v[i]; s2 += v[i] * v[i]; }
#pragma unroll
    for (int o = 16; o; o >>= 1) {
        s  += __shfl_xor_sync(~0u, s,  o);
        s2 += __shfl_xor_sync(~0u, s2, o);
    }
    __shared__ float sh[18];
    if ((t & 31) == 0) { sh[t >> 5] = s; sh[8 + (t >> 5)] = s2; }
    __syncthreads();
    if (t == 0) {
        float S = 0.f, S2 = 0.f;
#pragma unroll
        for (int i = 0; i < 8; ++i) { S += sh[i]; S2 += sh[8 + i]; }
        float mu = S * (1.f / IND);
        float ss = S2 - (float)IND * mu * mu;
        sh[16] = mu; sh[17] = rsqrtf(ss);
    }
    __syncthreads();
    float mu = sh[16], inv = sh[17];
#pragma unroll
    for (int i = 0; i < 4; ++i) dst[t + 256 * i] = (v[i] - mu) * inv;
}

// ---------------- main fused GEMM ----------------
// 8 warps: warps 0-3 compute out0 = x*W0^T, warps 4-7 compute out1 = y*W1^T.
// Per-GEMM warp grid 2x2, each warp owns a 64x64 output tile.

static __device__ __forceinline__ void load_stage(U32 sb, int slot, int kchunk,
                                                  const float* x, const float* y, int m0) {
    const int tid = threadIdx.x;
    const int ch = tid & 7;          // 16B chunk within 128B row
    const int r0 = tid >> 3;         // base row 0..31
    const U32 st = sb + SM_STAGE + slot * STAGE_BYTES;
    const int kofs = kchunk * KC + ch * 4;   // float offset within a 1024-float row
    const float* px  = x      + (size_t)(m0 + r0) * IND + kofs;
    const float* py  = y      + (size_t)(m0 + r0) * IND + kofs;
    const float* pw0 = g_W0n  + (size_t)r0 * IND + kofs;
    const float* pw1 = g_W1n  + (size_t)r0 * IND + kofs;
#pragma unroll
    for (int p = 0; p < 4; ++p) {
        const int row = r0 + 32 * p;
        const U32 c  = (U32)(ch * 16);
        const U32 so = (U32)(row * 128) + (c ^ (U32)((row & 7) << 4));
        cp16(st + TO_X  + so, px  + (size_t)(32 * p) * IND);
        cp16(st + TO_Y  + so, py  + (size_t)(32 * p) * IND);
        cp16(st + TO_W0 + so, pw0 + (size_t)(32 * p) * IND);
        cp16(st + TO_W1 + so, pw1 + (size_t)(32 * p) * IND);
    }
}

__global__ void __launch_bounds__(NTHR, 1)
gemm_kernel(const float* __restrict__ x, const float* __restrict__ y,
            const float* __restrict__ fc_bias, const float* __restrict__ a0,
            const float* __restrict__ a1, float* __restrict__ out) {
    extern __shared__ char smem[];
    const U32 sb = s2u(smem);
    const int tid = threadIdx.x;
    const int wid = tid >> 5, lid = tid & 31;
    const int m0 = blockIdx.x * BM;

    // start DRAM traffic immediately: prologue fills all NS stages
#pragma unroll
    for (int s = 0; s < NS; ++s) { load_stage(sb, s, s, x, y, m0); cp_commit(); }

    if (tid < 128) {
        float* sc = (float*)(smem + SM_COEF);
        sc[tid] = a0[tid]; sc[128 + tid] = a1[tid]; sc[256 + tid] = fc_bias[tid];
    }

    // warp role
    const int g1 = wid >> 2;             // 0: GEMM0 (x,W0), 1: GEMM1 (y,W1)
    const int wl = wid & 3;
    const int mw = wl & 1;               // m-half (64 rows)
    const int nw = wl >> 1;              // n-half (64 cols)

    // per-lane ldmatrix address components
    const int sel  = lid >> 3;           // which of the 4 8-row matrices
    const int lrow = lid & 7;
    // A: matrices (a0,a1,a2,a3) = (r0-7 k0-3),(r8-15 k0-3),(r0-7 k4-7),(r8-15 k4-7)
    const int aRowL = (sel & 1) * 8 + lrow;       // row within m16 tile
    const U32 aKb   = (U32)((sel >> 1) * 16);     // k byte offset 0 / 16
    // B: x4 group g covers n-tiles 4g..4g+3 (8 n-rows each) at a fixed k-half
    const int bRowL = sel * 8 + lrow;             // 0..31 within group

    U32 aRowOff[4], aXor[4];
#pragma unroll
    for (int mt = 0; mt < 4; ++mt) {
        int r = mw * 64 + mt * 16 + aRowL;
        aRowOff[mt] = (U32)(r * 128);
        aXor[mt]    = (U32)((r & 7) << 4);
    }
    U32 bRowOff[2], bXor[2];
#pragma unroll
    for (int g = 0; g < 2; ++g) {
        int r = nw * 64 + g * 32 + bRowL;
        bRowOff[g] = (U32)(r * 128);
        bXor[g]    = (U32)((r & 7) << 4);
    }

    float acc[4][8][4];
#pragma unroll
    for (int mt = 0; mt < 4; ++mt)
#pragma unroll
        for (int nt = 0; nt < 8; ++nt)
#pragma unroll
            for (int q = 0; q < 4; ++q) acc[mt][nt][q] = 0.f;

    const U32 toA = g1 ? TO_Y : TO_X;
    const U32 toB = g1 ? TO_W1 : TO_W0;

    for (int i = 0; i < NITER; ++i) {
        const int slot = i % NS;
        cp_wait<NS - 1>();
        __syncthreads();                       // stage i visible to all
        const U32 st = sb + SM_STAGE + (U32)(slot * STAGE_BYTES);
        const U32 abase = st + toA;
        const U32 bbase = st + toB;
#pragma unroll
        for (int ks = 0; ks < 4; ++ks) {       // 4 k8-steps per 32-float chunk
            const U32 kb = (U32)(ks * 32);     // byte offset of this k8 within the row
            U32 a[4][4];
#pragma unroll
            for (int mt = 0; mt < 4; ++mt)
                ldsm4(a[mt][0], a[mt][1], a[mt][2], a[mt][3],
                      abase + aRowOff[mt] + ((kb + aKb) ^ aXor[mt]));
            U32 b0[8], b1[8];
#pragma unroll
            for (int g = 0; g < 2; ++g) {
                ldsm4(b0[4 * g + 0], b0[4 * g + 1], b0[4 * g + 2], b0[4 * g + 3],
                      bbase + bRowOff[g] + ((kb + 0u)  ^ bXor[g]));
                ldsm4(b1[4 * g + 0], b1[4 * g + 1], b1[4 * g + 2], b1[4 * g + 3],
                      bbase + bRowOff[g] + ((kb + 16u) ^ bXor[g]));
            }
#pragma unroll
            for (int mt = 0; mt < 4; ++mt)
#pragma unroll
                for (int nt = 0; nt < 8; ++nt)
                    mma8(acc[mt][nt], a[mt][0], a[mt][1], a[mt][2], a[mt][3],
                         b0[nt], b1[nt]);
        }
        __syncthreads();                       // everyone done reading slot
        if (i + NS < NITER) load_stage(sb, slot, i + NS, x, y, m0);
        cp_commit();
    }
    __syncthreads();

    // ---------- epilogue ----------
    float* exch = (float*)(smem + SM_STAGE);   // 128 x EXP fp32 out0 exchange
    const float* sa0 = (const float*)(smem + SM_COEF);
    const float* sa1 = sa0 + 128;
    const float* sbs = sa0 + 256;

    const int rowb = mw * 64 + (lid >> 2);
    const int colb = nw * 64 + 2 * (lid & 3);

    if (!g1) {
        // out0: global + smem exchange
#pragma unroll
        for (int mt = 0; mt < 4; ++mt) {
            const int rl = rowb + mt * 16;
#pragma unroll
            for (int nt = 0; nt < 8; ++nt) {
                const int c = colb + nt * 8;
                float2 v0 = make_float2(acc[mt][nt][0], acc[mt][nt][1]);
                float2 v1 = make_float2(acc[mt][nt][2], acc[mt][nt][3]);
                *(float2*)(out + (size_t)(m0 + rl)     * ODIM + c) = v0;
                *(float2*)(out + (size_t)(m0 + rl + 8) * ODIM + c) = v1;
                *(float2*)(exch + rl * EXP + c)       = v0;
                *(float2*)(exch + (rl + 8) * EXP + c) = v1;
            }
        }
    } else {
        // out1: global
        float* o1 = out + (size_t)BATCHN * ODIM;
#pragma unroll
        for (int mt = 0; mt < 4; ++mt) {
            const int rl = rowb + mt * 16;
#pragma unroll
            for (int nt = 0; nt < 8; ++nt) {
                const int c = colb + nt * 8;
                *(float2*)(o1 + (size_t)(m0 + rl)     * ODIM + c) =
                    make_float2(acc[mt][nt][0], acc[mt][nt][1]);
                *(float2*)(o1 + (size_t)(m0 + rl + 8) * ODIM + c) =
                    make_float2(acc[mt][nt][2], acc[mt][nt][3]);
            }
        }
    }
    __syncthreads();

    if (g1) {
        // output = out0*a0 + out1*a1 + bias
        float* o2 = out + 2 * (size_t)BATCHN * ODIM;
#pragma unroll
        for (int mt = 0; mt < 4; ++mt) {
            const int rl = rowb + mt * 16;
#pragma unroll
            for (int nt = 0; nt < 8; ++nt) {
                const int c = colb + nt * 8;
                float2 p0 = *(const float2*)(exch + rl * EXP + c);
                float2 p1 = *(const float2*)(exch + (rl + 8) * EXP + c);
                const float A0x = sa0[c], A0y = sa0[c + 1];
                const float A1x = sa1[c], A1y = sa1[c + 1];
                const float Bx  = sbs[c], By  = sbs[c + 1];
                float2 r0, r1;
                r0.x = p0.x * A0x + acc[mt][nt][0] * A1x + Bx;
                r0.y = p0.y * A0y + acc[mt][nt][1] * A1y + By;
                r1.x = p1.x * A0x + acc[mt][nt][2] * A1x + Bx;
                r1.y = p1.y * A0y + acc[mt][nt][3] * A1y + By;
                *(float2*)(o2 + (size_t)(m0 + rl)     * ODIM + c) = r0;
                *(float2*)(o2 + (size_t)(m0 + rl + 8) * ODIM + c) = r1;
            }
        }
    }
}

// ---------------- launch ----------------

extern "C" void kernel_launch(void* const* d_in, const int* in_sizes, int n_in,
                              void* d_out, int out_size) {
    const float* x  = (const float*)d_in[0];
    const float* y  = (const float*)d_in[1];
    const float* fw = (const float*)d_in[2];
    const float* fb = (const float*)d_in[3];
    const float* a0 = (const float*)d_in[4];
    const float* a1 = (const float*)d_in[5];
    float* out = (float*)d_out;

    normalize_kernel<<<2 * ODIM, 256>>>(fw);

    cudaFuncSetAttribute(gemm_kernel, cudaFuncAttributeMaxDynamicSharedMemorySize, SMEM_TOTAL);
    gemm_kernel<<<BATCHN / BM, NTHR, SMEM_TOTAL>>>(x, y, fb, a0, a1, out);
}